// round 13
// baseline (speedup 1.0000x reference)
#include <cuda_runtime.h>
#include <cuda_fp16.h>
#include <cstdint>

#define BB 8
#define NN 4096
#define EE 2048
#define CC 128
#define EW (EE/32)   // 64 words per node row

// ---------------- device scratch ----------------
__device__ uint32_t g_hb [BB*NN*EW];  // H bit-packed, node-major
__device__ __half   g_efh[BB*EE*CC];  // post-fc normalized edge feats, fp16
__device__ __half   g_xh [BB*NN*CC];  // x in fp16
__device__ __half   g_wh [CC*CC];     // W in fp16

__device__ __forceinline__ uint2 f4h(float4 v){
    __half2 a = __floats2half2_rn(v.x, v.y);
    __half2 b = __floats2half2_rn(v.z, v.w);
    uint2 r;
    r.x = *reinterpret_cast<uint32_t*>(&a);
    r.y = *reinterpret_cast<uint32_t*>(&b);
    return r;
}
__device__ __forceinline__ __half2 u2h(uint32_t u){ return *reinterpret_cast<__half2*>(&u); }

__device__ __forceinline__ void cpa16(uint32_t dst, const void* src){
    asm volatile("cp.async.cg.shared.global [%0], [%1], 16;\n" :: "r"(dst), "l"(src));
}
__device__ __forceinline__ void cp_commit(){ asm volatile("cp.async.commit_group;\n"); }

__device__ __forceinline__ void ldsm4(uint32_t* r, uint32_t a){
    asm volatile("ldmatrix.sync.aligned.m8n8.x4.shared.b16 {%0,%1,%2,%3}, [%4];"
                 : "=r"(r[0]),"=r"(r[1]),"=r"(r[2]),"=r"(r[3]) : "r"(a));
}
__device__ __forceinline__ void ldsm4t(uint32_t* r, uint32_t a){
    asm volatile("ldmatrix.sync.aligned.m8n8.x4.trans.shared.b16 {%0,%1,%2,%3}, [%4];"
                 : "=r"(r[0]),"=r"(r[1]),"=r"(r[2]),"=r"(r[3]) : "r"(a));
}
__device__ __forceinline__ void mma16(float* c, const uint32_t* a, const uint32_t* b){
    asm volatile(
        "mma.sync.aligned.m16n8k16.row.col.f32.f16.f16.f32 "
        "{%0,%1,%2,%3}, {%4,%5,%6,%7}, {%8,%9}, {%0,%1,%2,%3};"
        : "+f"(c[0]),"+f"(c[1]),"+f"(c[2]),"+f"(c[3])
        : "r"(a[0]),"r"(a[1]),"r"(a[2]),"r"(a[3]),"r"(b[0]),"r"(b[1]));
}

// ---------------- prep: fp16-convert x and W ----------------
__global__ void prep_kernel(const float* __restrict__ x, const float* __restrict__ W){
    const int NX4 = BB*NN*CC/4, NW4 = CC*CC/4;
    int i = blockIdx.x*256 + threadIdx.x;
    if (i < NX4){
        ((uint2*)g_xh)[i] = f4h(((const float4*)x)[i]);
    } else if (i - NX4 < NW4){
        ((uint2*)g_wh)[i-NX4] = f4h(((const float4*)W)[i-NX4]);
    }
}

// ---------------- pack: H fp32 -> node-major bitmask (pure streaming) ----------------
// grid: BB*NN*EE/4/1024 blocks of 256 threads; each thread 4 float4s.
__global__ void pack_kernel(const float* __restrict__ H){
    const int t = threadIdx.x, lane = t & 31;
    const size_t base = (size_t)blockIdx.x*1024 + t;
    const float4* __restrict__ H4 = (const float4*)H;
    float4 v[4];
#pragma unroll
    for (int j=0;j<4;j++) v[j] = H4[base + (size_t)j*256];
#pragma unroll
    for (int j=0;j<4;j++){
        uint32_t nib = (v[j].x!=0.f?1u:0u) | (v[j].y!=0.f?2u:0u)
                     | (v[j].z!=0.f?4u:0u) | (v[j].w!=0.f?8u:0u);
        uint32_t word = nib << (4*(lane&7));
        word |= __shfl_xor_sync(0xffffffffu, word, 1);
        word |= __shfl_xor_sync(0xffffffffu, word, 2);
        word |= __shfl_xor_sync(0xffffffffu, word, 4);
        if ((lane&7)==0) g_hb[(base + (size_t)j*256)>>3] = word;
    }
}

// ================= v2e + fc fused (BM=64, K=4096), bitmask A =================
#define LDH 136                  // halves; [k][*] row stride (17x16B, ldmatrix conflict-free)
#define A0_BYTES (32*LDH*2)      // 8704 per A buffer (x2)
#define B_BYTES  (32*LDH*2)      // 8704 per B stage
#define NST0 5
#define LDMK 40                  // halves; [m][k=32] row stride
#define LDFA 136                 // halves; fc A-tile row stride
#define FC_A_OFF 0               // fc A_sm: 64*LDFA*2 = 17408 B
#define FC_W_OFF 17408           // fc W tile: 128*LDH*2 = 34816 -> ends 52224
#define SM0_BYTES (2*A0_BYTES + NST0*B_BYTES)   // 60928

__global__ void __launch_bounds__(256,2)
v2e_fc_kernel(const float* __restrict__ bias)
{
    constexpr int CHUNKS = NN/32;   // 128
    extern __shared__ char smraw[];
    __shared__ float deg_s[64];

    const int t=threadIdx.x, lane=t&31, wid=t>>5;
    const int b=blockIdx.y, m0g=blockIdx.x*64;
    const int wm=wid&1, wn=wid>>1;          // 2 row-groups x 4 col-groups of 32
    const int gid=lane>>2, tig=lane&3;
    const int grp=lane>>3, gj=lane&7;

    const uint32_t smb = (uint32_t)__cvta_generic_to_shared(smraw);

    float acc[2][4][4];
#pragma unroll
    for (int i=0;i<2;i++)
#pragma unroll
        for (int j=0;j<4;j++)
#pragma unroll
            for (int r=0;r<4;r++) acc[i][j][r]=0.f;
    __half2 dg2[2][2];
    dg2[0][0]=dg2[0][1]=dg2[1][0]=dg2[1][1]=__floats2half2_rn(0.f,0.f);

    const int a_k  = ((grp&2)?8:0) + gj;   // trans A k-offset
    const int a_m0 = ((grp&1)?8:0);        // trans A m-offset
    const int a_r  = ((grp&1)?8:0) + gj;   // non-trans A m-offset (fc)
    const int a_c  = ((grp&2)?8:0);        // non-trans A k-offset (fc)
    const int b_r  = ((grp&1)?8:0) + gj;   // B k-offset
    const int b_c  = (grp>>1)*8;           // B n-offset

    // bitmask source: node k = t>>3, edge-octet o = t&7
    const int ek = t>>3, eo = t&7;
    const uint32_t* __restrict__ wbase =
        g_hb + ((size_t)b*NN + ek)*EW + (m0g>>5) + (eo>>2);

    auto wld = [&](int kc){ return wbase[(size_t)kc*32*EW]; };

    auto expandA = [&](uint32_t word, int buf){
        const uint32_t bits = (word >> (8*(eo&3))) & 0xFFu;
        uint32_t h2[4];
#pragma unroll
        for (int p=0;p<4;p++){
            uint32_t v = (bits & (1u<<(2*p)))   ? 0x00003C00u : 0u;
            if (bits & (1u<<(2*p+1))) v |= 0x3C000000u;
            h2[p] = v;
        }
        const uint32_t d0 = smb + (uint32_t)(buf*A0_BYTES) + (uint32_t)((ek*LDH + eo*8)*2);
        asm volatile("st.shared.v4.b32 [%0], {%1,%2,%3,%4};"
                     :: "r"(d0), "r"(h2[0]), "r"(h2[1]), "r"(h2[2]), "r"(h2[3]));
    };

    auto stageB = [&](int kc, int buf){
        const int kg0 = kc*32;
        const uint32_t bB = smb + (uint32_t)(2*A0_BYTES + buf*B_BYTES);
        const __half* src0 = g_xh + ((size_t)b*NN + kg0)*CC;
#pragma unroll
        for (int i=0;i<2;i++){
            const int idx = t + 256*i;
            const int k = idx>>4, n8 = (idx&15)*8;
            cpa16(bB + (uint32_t)((k*LDH + n8)*2), src0 + (size_t)k*CC + n8);
        }
    };

    auto compute = [&](int abuf, int bbuf){
        const uint32_t aB = smb + (uint32_t)(abuf*A0_BYTES);
        const uint32_t bB = smb + (uint32_t)(2*A0_BYTES + bbuf*B_BYTES);
#pragma unroll
        for (int s=0;s<2;s++){
            const int k0 = s*16;
            uint32_t a[2][4], bf[4][2];
#pragma unroll
            for (int mt=0;mt<2;mt++)
                ldsm4t(a[mt], aB + (uint32_t)(((k0 + a_k)*LDH + wm*32 + mt*16 + a_m0)*2));
            if (wn==0){
#pragma unroll
                for (int mt=0;mt<2;mt++){
                    dg2[mt][0] = __hadd2(dg2[mt][0], __hadd2(u2h(a[mt][0]), u2h(a[mt][2])));
                    dg2[mt][1] = __hadd2(dg2[mt][1], __hadd2(u2h(a[mt][1]), u2h(a[mt][3])));
                }
            }
#pragma unroll
            for (int p=0;p<2;p++){
                uint32_t r[4];
                ldsm4t(r, bB + (uint32_t)(((k0 + b_r)*LDH + wn*32 + p*16 + b_c)*2));
                bf[2*p  ][0]=r[0]; bf[2*p  ][1]=r[1];
                bf[2*p+1][0]=r[2]; bf[2*p+1][1]=r[3];
            }
#pragma unroll
            for (int mt=0;mt<2;mt++)
#pragma unroll
                for (int j=0;j<4;j++)
                    mma16(acc[mt][j], a[mt], bf[j]);
        }
    };

    // ---- prologue ----
#pragma unroll
    for (int s=0; s<NST0-1; s++){
        if (s < CHUNKS) stageB(s, s);
        cp_commit();
    }
    uint32_t wa = wld(0);
    expandA(wa, 0);
    wa = wld(1);

    // ---- mainloop: one __syncthreads per chunk ----
    for (int kc=0; kc<CHUNKS; kc++){
        asm volatile("cp.async.wait_group %0;" :: "n"(NST0-2) : "memory");
        __syncthreads();   // B(kc) resident; A(kc) writes visible
        if (kc+NST0-1 < CHUNKS) stageB(kc+NST0-1, (kc+NST0-1)%NST0);
        cp_commit();
        if (kc+1 < CHUNKS){
            expandA(wa, (kc+1)&1);
            if (kc+2 < CHUNKS) wa = wld(kc+2);
        }
        compute(kc&1, kc%NST0);
    }
    asm volatile("cp.async.wait_group 0;" ::: "memory");
    __syncthreads();   // mainloop buffers dead; smem reused for fc

    // ---- stage W tile [k=128][n=128] ----
    {
        const uint32_t wB = smb + FC_W_OFF;
        const __half* src0 = g_wh;
#pragma unroll
        for (int i=0;i<8;i++){
            const int idx = t + 256*i;
            const int k = idx>>4, n8 = (idx&15)*8;
            cpa16(wB + (uint32_t)((k*LDH + n8)*2), src0 + (size_t)k*CC + n8);
        }
        cp_commit();
    }

    // ---- edge degrees -> deg_s ----
#pragma unroll
    for (int mt=0;mt<2;mt++)
#pragma unroll
        for (int rh=0;rh<2;rh++){
            float2 f = __half22float2(dg2[mt][rh]);
            float v = f.x + f.y;
            v += __shfl_xor_sync(0xffffffffu, v, 1);
            v += __shfl_xor_sync(0xffffffffu, v, 2);
            if (wn==0 && tig==0)
                deg_s[wm*32+mt*16+rh*8+gid] = v;
        }
    __syncthreads();

    // ---- store normalized fp16 A-tile [m=64][k=128], stride LDFA ----
    {
        const uint32_t aS = smb + FC_A_OFF;
#pragma unroll
        for (int mt=0;mt<2;mt++)
#pragma unroll
            for (int rh=0;rh<2;rh++){
                const int row = wm*32+mt*16+rh*8+gid;
                const float d = deg_s[row];
                const float inv = (d > 0.f) ? 1.f/d : 0.f;
#pragma unroll
                for (int j=0;j<4;j++){
                    const int col = wn*32 + j*8 + tig*2;
                    __half2 h = __floats2half2_rn(acc[mt][j][rh*2]*inv, acc[mt][j][rh*2+1]*inv);
                    asm volatile("st.shared.b32 [%0], %1;"
                                 :: "r"(aS + (uint32_t)((row*LDFA + col)*2)), "r"(*(uint32_t*)&h));
                }
            }
    }
    asm volatile("cp.async.wait_group 0;" ::: "memory");
    __syncthreads();

    // ---- fc GEMM: [64 x 128] = A_sm @ W ----
    float fcc[2][4][4];
#pragma unroll
    for (int i=0;i<2;i++)
#pragma unroll
        for (int j=0;j<4;j++)
#pragma unroll
            for (int r=0;r<4;r++) fcc[i][j][r]=0.f;
    {
        const uint32_t aS = smb + FC_A_OFF;
        const uint32_t wB = smb + FC_W_OFF;
#pragma unroll
        for (int ks=0; ks<8; ks++){
            const int k0 = ks*16;
            uint32_t a[2][4], bf[4][2];
#pragma unroll
            for (int mt=0;mt<2;mt++)
                ldsm4(a[mt], aS + (uint32_t)(((wm*32 + mt*16 + a_r)*LDFA + k0 + a_c)*2));
#pragma unroll
            for (int p=0;p<2;p++){
                uint32_t r[4];
                ldsm4t(r, wB + (uint32_t)(((k0 + b_r)*LDH + wn*32 + p*16 + b_c)*2));
                bf[2*p  ][0]=r[0]; bf[2*p  ][1]=r[1];
                bf[2*p+1][0]=r[2]; bf[2*p+1][1]=r[3];
            }
#pragma unroll
            for (int mt=0;mt<2;mt++)
#pragma unroll
                for (int j=0;j<4;j++)
                    mma16(fcc[mt][j], a[mt], bf[j]);
        }
    }

    // ---- +bias, mask, write g_efh ----
#pragma unroll
    for (int mt=0;mt<2;mt++)
#pragma unroll
        for (int rh=0;rh<2;rh++){
            const int row = wm*32+mt*16+rh*8+gid;
            const bool on = deg_s[row] > 0.f;
#pragma unroll
            for (int j=0;j<4;j++){
                const int col = wn*32 + j*8 + tig*2;
                float v0 = on ? fcc[mt][j][rh*2  ] + bias[col]   : 0.f;
                float v1 = on ? fcc[mt][j][rh*2+1] + bias[col+1] : 0.f;
                __half2 h = __floats2half2_rn(v0, v1);
                *(uint32_t*)&g_efh[((size_t)b*EE+m0g+row)*CC + col] = *(uint32_t*)&h;
            }
        }
}

// ================= e2v: bitmask A (2-buf) + cp.async B ring =================
#define A2_BYTES (128*LDMK*2)    // 10240 per A buffer (x2)
#define NST2 5
#define SM2_BYTES (2*A2_BYTES + NST2*B_BYTES)   // 64000

__global__ void __launch_bounds__(256,2)
e2v_kernel(float* __restrict__ out)
{
    constexpr int CHUNKS = EE/32;   // 64

    extern __shared__ char smraw[];
    __shared__ float deg_s[128];

    const int t=threadIdx.x, lane=t&31, wid=t>>5;
    const int b=blockIdx.y, m0g=blockIdx.x*128;
    const int wm=wid>>1, wn=wid&1, gid=lane>>2, tig=lane&3;
    const int grp=lane>>3, gj=lane&7;

    const uint32_t smb = (uint32_t)__cvta_generic_to_shared(smraw);

    float acc[2][8][4];
#pragma unroll
    for (int i=0;i<2;i++)
#pragma unroll
        for (int j=0;j<8;j++)
#pragma unroll
            for (int r=0;r<4;r++) acc[i][j][r]=0.f;

    const int a_r = ((grp&1)?8:0) + gj;
    const int a_c = ((grp&2)?8:0);
    const int b_r = ((grp&1)?8:0) + gj;
    const int b_c = (grp>>1)*8;

    const int am    = t>>1;
    const int ahalf = t&1;
    const uint32_t* __restrict__ wsrc = g_hb + ((size_t)b*NN + m0g + am)*EW;
    int degcnt = 0;

    auto stageB = [&](int kc, int buf){
        const int kg0 = kc*32;
        const uint32_t bB = smb + (uint32_t)(2*A2_BYTES + buf*B_BYTES);
        const __half* bsrc = g_efh + ((size_t)b*EE + kg0)*CC;
#pragma unroll
        for (int i=0;i<2;i++){
            const int idx = t + 256*i;
            const int k = idx>>4, n8 = (idx&15)*8;
            cpa16(bB + (uint32_t)((k*LDH + n8)*2), bsrc + (size_t)k*CC + n8);
        }
    };

    auto expandA = [&](uint32_t word, int buf){
        const uint32_t bits = (word >> (16*ahalf)) & 0xFFFFu;
        degcnt += __popc(bits);
        uint32_t h2[8];
#pragma unroll
        for (int p=0;p<8;p++){
            uint32_t v = (bits & (1u<<(2*p)))   ? 0x00003C00u : 0u;
            if (bits & (1u<<(2*p+1))) v |= 0x3C000000u;
            h2[p] = v;
        }
        const uint32_t d0 = smb + (uint32_t)(buf*A2_BYTES) + (uint32_t)((am*LDMK + ahalf*16)*2);
        asm volatile("st.shared.v4.b32 [%0], {%1,%2,%3,%4};"
                     :: "r"(d0), "r"(h2[0]), "r"(h2[1]), "r"(h2[2]), "r"(h2[3]));
        asm volatile("st.shared.v4.b32 [%0], {%1,%2,%3,%4};"
                     :: "r"(d0+16), "r"(h2[4]), "r"(h2[5]), "r"(h2[6]), "r"(h2[7]));
    };

    auto compute = [&](int abuf, int bbuf){
        const uint32_t aB = smb + (uint32_t)(abuf*A2_BYTES);
        const uint32_t bB = smb + (uint32_t)(2*A2_BYTES + bbuf*B_BYTES);
#pragma unroll
        for (int s=0;s<2;s++){
            const int k0 = s*16;
            uint32_t a[2][4], bf[8][2];
#pragma unroll
            for (int mt=0;mt<2;mt++)
                ldsm4(a[mt], aB + (uint32_t)(((wm*32 + mt*16 + a_r)*LDMK + k0 + a_c)*2));
#pragma unroll
            for (int p=0;p<4;p++){
                uint32_t r[4];
                ldsm4t(r, bB + (uint32_t)(((k0 + b_r)*LDH + wn*64 + p*16 + b_c)*2));
                bf[2*p  ][0]=r[0]; bf[2*p  ][1]=r[1];
                bf[2*p+1][0]=r[2]; bf[2*p+1][1]=r[3];
            }
#pragma unroll
            for (int mt=0;mt<2;mt++)
#pragma unroll
                for (int j=0;j<8;j++)
                    mma16(acc[mt][j], a[mt], bf[j]);
        }
    };

    // ---- prologue ----
#pragma unroll
    for (int s=0; s<NST2-1; s++){
        if (s < CHUNKS) stageB(s, s);
        cp_commit();
    }
    uint32_t wa = wsrc[0];
    expandA(wa, 0);
    wa = wsrc[1];

    // ---- mainloop: one __syncthreads per chunk ----
    for (int kc=0; kc<CHUNKS; kc++){
        asm volatile("cp.async.wait_group %0;" :: "n"(NST2-2) : "memory");
        __syncthreads();   // B(kc) resident; A(kc) visible
        if (kc+NST2-1 < CHUNKS) stageB(kc+NST2-1, (kc+NST2-1)%NST2);
        cp_commit();
        if (kc+1 < CHUNKS){
            expandA(wa, (kc+1)&1);
            if (kc+2 < CHUNKS) wa = wsrc[kc+2];
        }
        compute(kc&1, kc%NST2);
    }

    // node degrees: pair-reduce popc
    {
        int v = degcnt + __shfl_xor_sync(0xffffffffu, degcnt, 1);
        if ((t&1)==0) deg_s[am] = (float)v;
    }
    __syncthreads();

#pragma unroll
    for (int mt=0;mt<2;mt++)
#pragma unroll
        for (int rh=0;rh<2;rh++){
            const int row = wm*32+mt*16+rh*8+gid;
            const float d   = deg_s[row];
            const float inv = (d > 0.f) ? 1.f/d : 0.f;
#pragma unroll
            for (int j=0;j<8;j++){
                const int col = wn*64 + j*8 + tig*2;
                *(float2*)&out[((size_t)b*NN+m0g+row)*CC + col]
                    = make_float2(acc[mt][j][rh*2]*inv, acc[mt][j][rh*2+1]*inv);
            }
        }
}

// ---------------- launcher ----------------
extern "C" void kernel_launch(void* const* d_in, const int* in_sizes, int n_in,
                              void* d_out, int out_size)
{
    const float* x    = (const float*)d_in[0];
    const float* H    = (const float*)d_in[1];
    const float* W    = (const float*)d_in[2];
    const float* bias = (const float*)d_in[3];
    float* out = (float*)d_out;

    cudaFuncSetAttribute(v2e_fc_kernel, cudaFuncAttributeMaxDynamicSharedMemorySize, SM0_BYTES);
    cudaFuncSetAttribute(e2v_kernel,    cudaFuncAttributeMaxDynamicSharedMemorySize, SM2_BYTES);

    const int prep_blk = (BB*NN*CC/4 + CC*CC/4 + 255)/256;
    const int pack_blk = BB*NN*EE/4/1024;   // 16384

    prep_kernel  <<<prep_blk, 256>>>(x, W);
    pack_kernel  <<<pack_blk, 256>>>(H);
    v2e_fc_kernel<<<dim3(EE/64,  BB), 256, SM0_BYTES>>>(bias);
    e2v_kernel   <<<dim3(NN/128, BB), 256, SM2_BYTES>>>(out);
}